// round 3
// baseline (speedup 1.0000x reference)
#include <cuda_runtime.h>
#include <math.h>

// ---------------- problem constants ----------------
#define B_     32
#define N_     4096
#define F_     768
#define DIM_   256
#define H_     4
#define DH_    64
#define KSLOT_ 16
#define IH_    64          // KSLOT_*H_
#define ITERS_ 3
#define EPSW_  1e-8f
#define SCALE_ 0.125f      // DH^-0.5

// ---------------- scratch (device globals; no allocation) ----------------
__device__ float g_xn[100663296];          // [131072][768]  ln(inputs)
__device__ float g_k [33554432];           // [131072][256]
__device__ float g_v [33554432];           // [131072][256]
__device__ float g_vsum[B_*DIM_];          // [32][256]
__device__ float g_slots[B_*KSLOT_*DIM_];  // [512][256]
__device__ float g_q    [B_*KSLOT_*DIM_];  // [512][256] (pre-scaled by SCALE_)
__device__ float g_attn [8388608];         // [32][64][4096]
__device__ float g_S    [B_*IH_];          // [32][64] attn row sums over j
__device__ float g_upd  [B_*IH_*DH_];      // [32][64][64] sum_j attn*v

// ---------------- helpers ----------------
__device__ __forceinline__ float2 blockReduceSum2(float a, float b) {
    // 256 threads assumed
    __shared__ float sa[8], sb[8];
    int lane = threadIdx.x & 31, w = threadIdx.x >> 5;
#pragma unroll
    for (int o = 16; o; o >>= 1) {
        a += __shfl_down_sync(0xffffffffu, a, o);
        b += __shfl_down_sync(0xffffffffu, b, o);
    }
    if (lane == 0) { sa[w] = a; sb[w] = b; }
    __syncthreads();
    if (w == 0) {
        float aa = (lane < 8) ? sa[lane] : 0.f;
        float bb = (lane < 8) ? sb[lane] : 0.f;
#pragma unroll
        for (int o = 4; o; o >>= 1) {
            aa += __shfl_down_sync(0xffffffffu, aa, o);
            bb += __shfl_down_sync(0xffffffffu, bb, o);
        }
        if (lane == 0) { sa[0] = aa; sb[0] = bb; }
    }
    __syncthreads();
    float2 r = make_float2(sa[0], sb[0]);
    __syncthreads();
    return r;
}

// ---------------- K1: LayerNorm over FEAT=768 ----------------
__global__ __launch_bounds__(256) void ln_in_kernel(const float* __restrict__ x,
                                                    const float* __restrict__ g,
                                                    const float* __restrict__ bb) {
    size_t row = blockIdx.x;
    const float* xr = x + row * F_;
    int t = threadIdx.x;
    float v0 = xr[t], v1 = xr[t + 256], v2 = xr[t + 512];
    float2 r = blockReduceSum2(v0 + v1 + v2, v0 * v0 + v1 * v1 + v2 * v2);
    float mean = r.x * (1.f / 768.f);
    float var  = r.y * (1.f / 768.f) - mean * mean;
    float inv  = rsqrtf(var + 1e-5f);
    float* o = g_xn + row * F_;
    o[t]       = (v0 - mean) * inv * g[t]       + bb[t];
    o[t + 256] = (v1 - mean) * inv * g[t + 256] + bb[t + 256];
    o[t + 512] = (v2 - mean) * inv * g[t + 512] + bb[t + 512];
}

// ---------------- K2: fp32 GEMM  C[131072,512] = xn @ [Wk;Wv]^T ----------------
// BM=128, BN=64, BK=16, 256 threads, 8x4 micro-tile
__global__ __launch_bounds__(256) void proj_gemm_kernel(const float* __restrict__ Wk,
                                                        const float* __restrict__ Wv) {
    __shared__ float As[16 * 132];
    __shared__ float Bs[16 * 68];
    int bx = blockIdx.x, by = blockIdx.y;
    int t = threadIdx.x;
    size_t m0 = (size_t)by * 128;
    const float* Wbase = (bx < 4) ? (Wk + (size_t)bx * 64 * 768)
                                  : (Wv + (size_t)(bx - 4) * 64 * 768);
    int tx = t & 15, ty = t >> 4;
    float acc[8][4];
#pragma unroll
    for (int i = 0; i < 8; i++)
#pragma unroll
        for (int j = 0; j < 4; j++) acc[i][j] = 0.f;

    for (int kt = 0; kt < 48; kt++) {
#pragma unroll
        for (int r = 0; r < 2; r++) {
            int s = t + 256 * r;
            int m = s >> 2, kc = s & 3;
            float4 a = *(const float4*)&g_xn[(m0 + m) * 768 + kt * 16 + kc * 4];
            As[(kc * 4 + 0) * 132 + m] = a.x;
            As[(kc * 4 + 1) * 132 + m] = a.y;
            As[(kc * 4 + 2) * 132 + m] = a.z;
            As[(kc * 4 + 3) * 132 + m] = a.w;
        }
        {
            int n = t >> 2, kc = t & 3;
            float4 b4 = *(const float4*)&Wbase[(size_t)n * 768 + kt * 16 + kc * 4];
            Bs[(kc * 4 + 0) * 68 + n] = b4.x;
            Bs[(kc * 4 + 1) * 68 + n] = b4.y;
            Bs[(kc * 4 + 2) * 68 + n] = b4.z;
            Bs[(kc * 4 + 3) * 68 + n] = b4.w;
        }
        __syncthreads();
#pragma unroll
        for (int kk = 0; kk < 16; kk++) {
            float4 a0 = *(float4*)&As[kk * 132 + ty * 8];
            float4 a1 = *(float4*)&As[kk * 132 + ty * 8 + 4];
            float4 b4 = *(float4*)&Bs[kk * 68 + tx * 4];
            float am[8] = {a0.x, a0.y, a0.z, a0.w, a1.x, a1.y, a1.z, a1.w};
            float bn[4] = {b4.x, b4.y, b4.z, b4.w};
#pragma unroll
            for (int i = 0; i < 8; i++)
#pragma unroll
                for (int j = 0; j < 4; j++) acc[i][j] += am[i] * bn[j];
        }
        __syncthreads();
    }
    float* Obase = (bx < 4) ? g_k : g_v;
    int colbase = (bx & 3) * 64 + tx * 4;
#pragma unroll
    for (int i = 0; i < 8; i++) {
        float4 o = make_float4(acc[i][0], acc[i][1], acc[i][2], acc[i][3]);
        *(float4*)&Obase[(m0 + ty * 8 + i) * 256 + colbase] = o;
    }
}

// ---------------- K2b: per-batch column sums of v ----------------
__global__ __launch_bounds__(256) void vsum_kernel() {
    int b = blockIdx.x, t = threadIdx.x;
    const float* vp = g_v + (size_t)b * N_ * DIM_ + t;
    float s = 0.f;
    for (int j = 0; j < N_; j++) s += vp[(size_t)j * DIM_];
    g_vsum[b * DIM_ + t] = s;
}

// ---------------- zero per-iteration accumulators ----------------
__global__ void zero_kernel() {
    int idx = blockIdx.x * blockDim.x + threadIdx.x;  // 520*256 = 133120
    if (idx < B_ * IH_) g_S[idx] = 0.f;
    else g_upd[idx - B_ * IH_] = 0.f;
}

// ---------------- K3: slots LN + q projection (scaled) ----------------
__global__ __launch_bounds__(256) void slot_q_kernel(const float* __restrict__ g,
                                                     const float* __restrict__ bb,
                                                     const float* __restrict__ Wq) {
    __shared__ float sn[256];
    int row = blockIdx.x, t = threadIdx.x;
    float sv = g_slots[row * 256 + t];
    float2 r = blockReduceSum2(sv, sv * sv);
    float mean = r.x * (1.f / 256.f);
    float var  = r.y * (1.f / 256.f) - mean * mean;
    float inv  = rsqrtf(var + 1e-5f);
    sn[t] = (sv - mean) * inv * g[t] + bb[t];
    __syncthreads();
    const float4* w4 = (const float4*)(Wq + (size_t)t * 256);
    float acc = 0.f;
#pragma unroll 8
    for (int c = 0; c < 64; c++) {
        float4 w = w4[c];
        acc += w.x * sn[4 * c] + w.y * sn[4 * c + 1] + w.z * sn[4 * c + 2] + w.w * sn[4 * c + 3];
    }
    g_q[row * 256 + t] = acc * SCALE_;
}

// ---------------- K4: dots + joint softmax + attn write + row sums ----------------
#define DOTS_SMEM ((64 * 65 + 64 * 256 + 64 * 65) * 4)
__global__ __launch_bounds__(256) void dots_kernel(float* __restrict__ attn_out) {
    extern __shared__ float sm[];
    float* qs = sm;              // [64][65]  (ih, d) padded
    float* kt = sm + 64 * 65;    // [64][256] (j, c)
    float* ds = kt + 64 * 256;   // [64][65]  (ih, j) padded
    int b = blockIdx.y, jt = blockIdx.x, t = threadIdx.x;

    for (int idx = t; idx < 4096; idx += 256) {
        int i = idx >> 8, c = idx & 255;
        qs[(i * 4 + (c >> 6)) * 65 + (c & 63)] = g_q[(b * KSLOT_ + i) * 256 + c];
    }
    const float4* kb = (const float4*)(g_k + ((size_t)b * N_ + jt * 64) * DIM_);
    for (int idx = t; idx < 4096; idx += 256) ((float4*)kt)[idx] = kb[idx];
    __syncthreads();

    int i = t & 15, j0 = t >> 4;
    const float* q0 = qs + (i * 4 + 0) * 65;
    const float* q1 = qs + (i * 4 + 1) * 65;
    const float* q2 = qs + (i * 4 + 2) * 65;
    const float* q3 = qs + (i * 4 + 3) * 65;
#pragma unroll
    for (int jm = 0; jm < 4; jm++) {
        int j = j0 + jm * 16;
        const float* kr = kt + j * 256;
        float a0 = 0.f, a1 = 0.f, a2 = 0.f, a3 = 0.f;
#pragma unroll 16
        for (int d = 0; d < 64; d++) {
            a0 += q0[d] * kr[d];
            a1 += q1[d] * kr[64 + d];
            a2 += q2[d] * kr[128 + d];
            a3 += q3[d] * kr[192 + d];
        }
        ds[(i * 4 + 0) * 65 + j] = a0;
        ds[(i * 4 + 1) * 65 + j] = a1;
        ds[(i * 4 + 2) * 65 + j] = a2;
        ds[(i * 4 + 3) * 65 + j] = a3;
    }
    __syncthreads();

    if (t < 64) {  // softmax over the 64 (slot,head) values at column j=t
        float mx = -1e30f;
        for (int ih = 0; ih < 64; ih++) mx = fmaxf(mx, ds[ih * 65 + t]);
        float sum = 0.f;
        for (int ih = 0; ih < 64; ih++) {
            float e = expf(ds[ih * 65 + t] - mx);
            ds[ih * 65 + t] = e;
            sum += e;
        }
        float inv = 1.f / sum;
        for (int ih = 0; ih < 64; ih++) ds[ih * 65 + t] *= inv;
    }
    __syncthreads();

    for (int idx = t; idx < 4096; idx += 256) {
        int ih = idx >> 6, jl = idx & 63;
        g_attn[((size_t)b * IH_ + ih) * N_ + jt * 64 + jl] = ds[ih * 65 + jl];
    }
    if (t < 64) {
        float s = 0.f;
        for (int jl = 0; jl < 64; jl++) s += ds[t * 65 + jl];
        atomicAdd(&g_S[b * IH_ + t], s);
    }
    if (attn_out) {  // last iteration: attn.mean over heads
        for (int idx = t; idx < 1024; idx += 256) {
            int i2 = idx >> 6, jl = idx & 63;
            float m = 0.25f * (ds[(i2 * 4 + 0) * 65 + jl] + ds[(i2 * 4 + 1) * 65 + jl] +
                               ds[(i2 * 4 + 2) * 65 + jl] + ds[(i2 * 4 + 3) * 65 + jl]);
            attn_out[((size_t)b * KSLOT_ + i2) * N_ + jt * 64 + jl] = m;
        }
    }
}

// ---------------- K4b: updates accumulation  sum_j attn * v ----------------
#define UPD_SMEM ((64 * 65 + 64 * 256) * 4)
__global__ __launch_bounds__(256) void upd_kernel() {
    extern __shared__ float sm[];
    float* a_s = sm;             // [64][65]
    float* v_s = sm + 64 * 65;   // [64][256]
    int b = blockIdx.y, jc = blockIdx.x, t = threadIdx.x;
    int d = t & 63, ihg = t >> 6;
    float acc[16];
#pragma unroll
    for (int m = 0; m < 16; m++) acc[m] = 0.f;

    for (int sub = 0; sub < 8; sub++) {
        int j0 = jc * 512 + sub * 64;
        __syncthreads();
        for (int idx = t; idx < 4096; idx += 256) {
            int ih = idx >> 6, jl = idx & 63;
            a_s[ih * 65 + jl] = g_attn[((size_t)b * IH_ + ih) * N_ + j0 + jl];
        }
        const float4* vb = (const float4*)(g_v + ((size_t)b * N_ + j0) * DIM_);
        for (int idx = t; idx < 4096; idx += 256) ((float4*)v_s)[idx] = vb[idx];
        __syncthreads();
#pragma unroll 4
        for (int jl = 0; jl < 64; jl++) {
            float vh[4] = {v_s[jl * 256 + d], v_s[jl * 256 + 64 + d],
                           v_s[jl * 256 + 128 + d], v_s[jl * 256 + 192 + d]};
#pragma unroll
            for (int m = 0; m < 16; m++)
                acc[m] += a_s[(ihg * 16 + m) * 65 + jl] * vh[m & 3];
        }
    }
#pragma unroll
    for (int m = 0; m < 16; m++)
        atomicAdd(&g_upd[(b * IH_ + ihg * 16 + m) * DH_ + d], acc[m]);
}

// ---------------- K5a: finalize updates + GRU cell ----------------
__global__ __launch_bounds__(256) void gru_kernel(const float* __restrict__ w_ih,
                                                  const float* __restrict__ w_hh,
                                                  const float* __restrict__ b_ih,
                                                  const float* __restrict__ b_hh) {
    __shared__ float u[256];
    __shared__ float hp[256];
    int row = blockIdx.x, t = threadIdx.x;
    int b = row >> 4, i = row & 15;
    int h = t >> 6;
    int ih = i * 4 + h;
    float upd = g_upd[(b * IH_ + ih) * DH_ + (t & 63)];
    float Sv  = g_S[b * IH_ + ih];
    u[t]  = (upd + EPSW_ * g_vsum[b * 256 + t]) / (Sv + (float)N_ * EPSW_);
    hp[t] = g_slots[row * 256 + t];
    __syncthreads();
    float gi[3], gh[3];
#pragma unroll
    for (int x = 0; x < 3; x++) {
        const float4* wi = (const float4*)(w_ih + (size_t)(x * 256 + t) * 256);
        const float4* wh = (const float4*)(w_hh + (size_t)(x * 256 + t) * 256);
        float si = 0.f, sh = 0.f;
#pragma unroll 8
        for (int c = 0; c < 64; c++) {
            float4 a = wi[c], dd = wh[c];
            si += a.x * u[4 * c] + a.y * u[4 * c + 1] + a.z * u[4 * c + 2] + a.w * u[4 * c + 3];
            sh += dd.x * hp[4 * c] + dd.y * hp[4 * c + 1] + dd.z * hp[4 * c + 2] + dd.w * hp[4 * c + 3];
        }
        gi[x] = si + b_ih[x * 256 + t];
        gh[x] = sh + b_hh[x * 256 + t];
    }
    float rg = 1.f / (1.f + expf(-(gi[0] + gh[0])));
    float z  = 1.f / (1.f + expf(-(gi[1] + gh[1])));
    float n  = tanhf(gi[2] + rg * gh[2]);
    g_slots[row * 256 + t] = (1.f - z) * n + z * hp[t];
}

// ---------------- K5b: FF (LN -> GELU MLP -> residual) ----------------
__global__ __launch_bounds__(256) void ff_kernel(const float* __restrict__ g,
                                                 const float* __restrict__ bb,
                                                 const float* __restrict__ W1,
                                                 const float* __restrict__ b1,
                                                 const float* __restrict__ W2,
                                                 const float* __restrict__ b2) {
    __shared__ float s0[256];
    __shared__ float h1[256];
    __shared__ float a_s[1024];
    int row = blockIdx.x, t = threadIdx.x;
    float sv = g_slots[row * 256 + t];
    s0[t] = sv;
    float2 r = blockReduceSum2(sv, sv * sv);
    float mean = r.x * (1.f / 256.f);
    float var  = r.y * (1.f / 256.f) - mean * mean;
    float inv  = rsqrtf(var + 1e-5f);
    h1[t] = (sv - mean) * inv * g[t] + bb[t];
    __syncthreads();
#pragma unroll
    for (int m = 0; m < 4; m++) {
        int j = m * 256 + t;
        const float4* w4 = (const float4*)(W1 + (size_t)j * 256);
        float acc = b1[j];
#pragma unroll 8
        for (int c = 0; c < 64; c++) {
            float4 w = w4[c];
            acc += w.x * h1[4 * c] + w.y * h1[4 * c + 1] + w.z * h1[4 * c + 2] + w.w * h1[4 * c + 3];
        }
        a_s[j] = 0.5f * acc * (1.f + erff(acc * 0.70710678118654752f));
    }
    __syncthreads();
    const float4* w4 = (const float4*)(W2 + (size_t)t * 1024);
    float acc = b2[t];
#pragma unroll 8
    for (int c = 0; c < 256; c++) {
        float4 w = w4[c];
        acc += w.x * a_s[4 * c] + w.y * a_s[4 * c + 1] + w.z * a_s[4 * c + 2] + w.w * a_s[4 * c + 3];
    }
    g_slots[row * 256 + t] = s0[t] + acc;
}

// ---------------- launch ----------------
extern "C" void kernel_launch(void* const* d_in, const int* in_sizes, int n_in,
                              void* d_out, int out_size) {
    const float* inputs  = (const float*)d_in[0];
    const float* cond    = (const float*)d_in[1];
    const float* to_q_w  = (const float*)d_in[2];
    const float* to_k_w  = (const float*)d_in[3];
    const float* to_v_w  = (const float*)d_in[4];
    const float* w_ih    = (const float*)d_in[5];
    const float* w_hh    = (const float*)d_in[6];
    const float* b_ih    = (const float*)d_in[7];
    const float* b_hh    = (const float*)d_in[8];
    const float* ln_in_g = (const float*)d_in[9];
    const float* ln_in_b = (const float*)d_in[10];
    const float* ln_s_g  = (const float*)d_in[11];
    const float* ln_s_b  = (const float*)d_in[12];
    const float* ff_g    = (const float*)d_in[13];
    const float* ff_b    = (const float*)d_in[14];
    const float* ff_w1   = (const float*)d_in[15];
    const float* ff_b1   = (const float*)d_in[16];
    const float* ff_w2   = (const float*)d_in[17];
    const float* ff_b2   = (const float*)d_in[18];

    float* out_slots = (float*)d_out;
    float* out_attn  = out_slots + (size_t)B_ * KSLOT_ * DIM_;  // then [B,K,N]

    void* pSlots = nullptr;
    cudaGetSymbolAddress(&pSlots, g_slots);

    cudaFuncSetAttribute(dots_kernel, cudaFuncAttributeMaxDynamicSharedMemorySize, DOTS_SMEM);
    cudaFuncSetAttribute(upd_kernel,  cudaFuncAttributeMaxDynamicSharedMemorySize, UPD_SMEM);

    ln_in_kernel<<<B_ * N_, 256>>>(inputs, ln_in_g, ln_in_b);
    proj_gemm_kernel<<<dim3(8, 1024), 256>>>(to_k_w, to_v_w);
    vsum_kernel<<<B_, 256>>>();
    cudaMemcpyAsync(pSlots, cond, (size_t)B_ * KSLOT_ * DIM_ * sizeof(float),
                    cudaMemcpyDeviceToDevice, 0);

    for (int it = 0; it < ITERS_; it++) {
        zero_kernel<<<520, 256>>>();
        slot_q_kernel<<<B_ * KSLOT_, 256>>>(ln_s_g, ln_s_b, to_q_w);
        dots_kernel<<<dim3(64, B_), 256, DOTS_SMEM>>>(it == ITERS_ - 1 ? out_attn : (float*)nullptr);
        upd_kernel<<<dim3(8, B_), 256, UPD_SMEM>>>();
        gru_kernel<<<B_ * KSLOT_, 256>>>(w_ih, w_hh, b_ih, b_hh);
        ff_kernel<<<B_ * KSLOT_, 256>>>(ff_g, ff_b, ff_w1, ff_b1, ff_w2, ff_b2);
    }
    cudaMemcpyAsync(d_out, pSlots, (size_t)B_ * KSLOT_ * DIM_ * sizeof(float),
                    cudaMemcpyDeviceToDevice, 0);
}

// round 6
// speedup vs baseline: 2.0734x; 2.0734x over previous
#include <cuda_runtime.h>
#include <cuda_bf16.h>
#include <math.h>
#include <stdint.h>

// ---------------- problem constants ----------------
#define B_     32
#define N_     4096
#define F_     768
#define DIM_   256
#define H_     4
#define DH_    64
#define KSLOT_ 16
#define IH_    64
#define ITERS_ 3
#define EPSW_  1e-8f
#define SCALE_ 0.125f

// ---------------- scratch (device globals; no allocation) ----------------
__device__ __nv_bfloat16 g_xhi[100663296];   // [131072][768]
__device__ __nv_bfloat16 g_xlo[100663296];
__device__ __nv_bfloat16 g_wb_hi[393216];    // [512][768]  rows 0-255 Wk, 256-511 Wv
__device__ __nv_bfloat16 g_wb_lo[393216];
__device__ float g_k [33554432];             // [131072][256]
__device__ float g_v [33554432];
__device__ float g_vsum[B_*DIM_];
__device__ float g_slots[B_*KSLOT_*DIM_];
__device__ float g_q    [B_*KSLOT_*DIM_];
__device__ float g_attn [8388608];           // [32][64][4096]
__device__ float g_S    [B_*IH_];
__device__ float g_upd  [B_*IH_*DH_];

// single extern shared symbol, one type everywhere
extern __shared__ float dynsm[];

// ---------------- PTX helpers (sm_80-baseline only) ----------------
__device__ __forceinline__ uint32_t smem_u32(const void* p) {
    uint32_t a;
    asm("{ .reg .u64 t; cvta.to.shared.u64 t, %1; cvt.u32.u64 %0, t; }" : "=r"(a) : "l"(p));
    return a;
}
#define CP_ASYNC16(dst, src) \
    asm volatile("cp.async.cg.shared.global [%0], [%1], 16;" :: "r"(dst), "l"(src))
#define CP_COMMIT()  asm volatile("cp.async.commit_group;")
#define CP_WAIT0()   asm volatile("cp.async.wait_group 0;")
#define CP_WAIT1()   asm volatile("cp.async.wait_group 1;")

#define LDSM4(r0, r1, r2, r3, a) \
    asm volatile("ldmatrix.sync.aligned.m8n8.x4.shared.b16 {%0,%1,%2,%3}, [%4];" \
        : "=r"(r0), "=r"(r1), "=r"(r2), "=r"(r3) : "r"(a))

#define MMA16816(c, a, b) \
    asm volatile("mma.sync.aligned.m16n8k16.row.col.f32.bf16.bf16.f32 " \
        "{%0,%1,%2,%3}, {%4,%5,%6,%7}, {%8,%9}, {%0,%1,%2,%3};" \
        : "+f"((c)[0]), "+f"((c)[1]), "+f"((c)[2]), "+f"((c)[3]) \
        : "r"((a)[0]), "r"((a)[1]), "r"((a)[2]), "r"((a)[3]), "r"((b)[0]), "r"((b)[1]))

// ---------------- block reduce (256 threads) ----------------
__device__ __forceinline__ float2 blockReduceSum2(float a, float b) {
    __shared__ float sa[8], sb[8];
    int lane = threadIdx.x & 31, w = threadIdx.x >> 5;
#pragma unroll
    for (int o = 16; o; o >>= 1) {
        a += __shfl_down_sync(0xffffffffu, a, o);
        b += __shfl_down_sync(0xffffffffu, b, o);
    }
    if (lane == 0) { sa[w] = a; sb[w] = b; }
    __syncthreads();
    if (w == 0) {
        float aa = (lane < 8) ? sa[lane] : 0.f;
        float bb = (lane < 8) ? sb[lane] : 0.f;
#pragma unroll
        for (int o = 4; o; o >>= 1) {
            aa += __shfl_down_sync(0xffffffffu, aa, o);
            bb += __shfl_down_sync(0xffffffffu, bb, o);
        }
        if (lane == 0) { sa[0] = aa; sb[0] = bb; }
    }
    __syncthreads();
    float2 r = make_float2(sa[0], sb[0]);
    __syncthreads();
    return r;
}

// ---------------- K1: LayerNorm over 768 -> split bf16 hi/lo ----------------
__global__ __launch_bounds__(256) void ln_in_kernel(const float* __restrict__ x,
                                                    const float* __restrict__ g,
                                                    const float* __restrict__ bb) {
    size_t row = blockIdx.x;
    const float* xr = x + row * F_;
    int t = threadIdx.x;
    float v0 = xr[t], v1 = xr[t + 256], v2 = xr[t + 512];
    float2 r = blockReduceSum2(v0 + v1 + v2, v0 * v0 + v1 * v1 + v2 * v2);
    float mean = r.x * (1.f / 768.f);
    float var  = r.y * (1.f / 768.f) - mean * mean;
    float inv  = rsqrtf(var + 1e-5f);
    __nv_bfloat16* oh = g_xhi + row * F_;
    __nv_bfloat16* ol = g_xlo + row * F_;
#pragma unroll
    for (int e = 0; e < 3; e++) {
        int c = t + 256 * e;
        float vv = (e == 0 ? v0 : (e == 1 ? v1 : v2));
        float y = (vv - mean) * inv * g[c] + bb[c];
        __nv_bfloat16 h = __float2bfloat16(y);
        oh[c] = h;
        ol[c] = __float2bfloat16(y - __bfloat162float(h));
    }
}

// ---------------- weight split-convert ----------------
__global__ void wconv_kernel(const float* __restrict__ Wk, const float* __restrict__ Wv) {
    int idx = blockIdx.x * 1024 + threadIdx.x;   // < 393216
    float w = (idx < 196608) ? Wk[idx] : Wv[idx - 196608];
    __nv_bfloat16 h = __float2bfloat16(w);
    g_wb_hi[idx] = h;
    g_wb_lo[idx] = __float2bfloat16(w - __bfloat162float(h));
}

// ---------------- split-bf16 mma.sync projection GEMM ----------------
// C[131072,512] = xn @ W^T.  grid (4, 1024): bx = 128-col tile, by = 128-row tile.
// BM=128, BN=128, BK=64, 256 threads (8 warps, warp tile 64x32), cp.async 2-stage.
#define PSTG   65536                       // A_hi 16K | A_lo 16K | B_hi 16K | B_lo 16K
#define PROJ_SMEM (2 * PSTG)

__device__ __forceinline__ void proj_fill_async(uint32_t stg, int kt, size_t m0,
                                                int n0, int t) {
#pragma unroll
    for (int i = 0; i < 4; i++) {
        int idx = t + 256 * i;                 // 0..1023 chunks of 16B
        int row = idx >> 3, c = idx & 7;
        uint32_t off = row * 128 + ((c ^ (row & 7)) << 4);
        size_t aoff = ((m0 + row) * 768 + (size_t)kt * 64 + c * 8) * 2;
        size_t boff = (((size_t)(n0 + row)) * 768 + (size_t)kt * 64 + c * 8) * 2;
        CP_ASYNC16(stg + off,         (const char*)g_xhi   + aoff);
        CP_ASYNC16(stg + 16384 + off, (const char*)g_xlo   + aoff);
        CP_ASYNC16(stg + 32768 + off, (const char*)g_wb_hi + boff);
        CP_ASYNC16(stg + 49152 + off, (const char*)g_wb_lo + boff);
    }
}

__global__ __launch_bounds__(256) void proj_mma_kernel() {
    uint32_t base = smem_u32(dynsm);
    const int t = threadIdx.x;
    const int lane = t & 31, wid = t >> 5;
    const int wm = wid & 1, wn = wid >> 1;      // warp grid 2x4
    const int bx = blockIdx.x;
    const size_t m0 = (size_t)blockIdx.y * 128;
    const int n0 = bx * 128;

    float c[4][4][4];
#pragma unroll
    for (int mi = 0; mi < 4; mi++)
#pragma unroll
        for (int ni = 0; ni < 4; ni++)
#pragma unroll
            for (int e = 0; e < 4; e++) c[mi][ni][e] = 0.f;

    const int g = lane >> 3, rin = lane & 7;

    proj_fill_async(base, 0, m0, n0, t);
    CP_COMMIT();

    for (int kt = 0; kt < 12; kt++) {
        uint32_t cur = base + (uint32_t)(kt & 1) * PSTG;
        if (kt + 1 < 12) {
            proj_fill_async(base + (uint32_t)((kt + 1) & 1) * PSTG, kt + 1, m0, n0, t);
            CP_COMMIT();
            CP_WAIT1();
        } else {
            CP_WAIT0();
        }
        __syncthreads();

#pragma unroll
        for (int ks = 0; ks < 4; ks++) {
            uint32_t aHi[4][4], aLo[4][4], bHi[4][2], bLo[4][2];
#pragma unroll
            for (int mi = 0; mi < 4; mi++) {
                int row = wm * 64 + mi * 16 + (g & 1) * 8 + rin;
                int cc = ks * 2 + (g >> 1);
                uint32_t ad = cur + row * 128 + ((cc ^ (row & 7)) << 4);
                LDSM4(aHi[mi][0], aHi[mi][1], aHi[mi][2], aHi[mi][3], ad);
                LDSM4(aLo[mi][0], aLo[mi][1], aLo[mi][2], aLo[mi][3], ad + 16384);
            }
#pragma unroll
            for (int bi = 0; bi < 2; bi++) {
                int nr = wn * 32 + bi * 16 + (g >> 1) * 8 + rin;
                int cc = ks * 2 + (g & 1);
                uint32_t bd = cur + 32768 + nr * 128 + ((cc ^ (nr & 7)) << 4);
                uint32_t r0, r1, r2, r3;
                LDSM4(r0, r1, r2, r3, bd);
                bHi[bi * 2][0] = r0; bHi[bi * 2][1] = r1;
                bHi[bi * 2 + 1][0] = r2; bHi[bi * 2 + 1][1] = r3;
                LDSM4(r0, r1, r2, r3, bd + 16384);
                bLo[bi * 2][0] = r0; bLo[bi * 2][1] = r1;
                bLo[bi * 2 + 1][0] = r2; bLo[bi * 2 + 1][1] = r3;
            }
#pragma unroll
            for (int mi = 0; mi < 4; mi++)
#pragma unroll
                for (int ni = 0; ni < 4; ni++) {
                    MMA16816(c[mi][ni], aHi[mi], bHi[ni]);
                    MMA16816(c[mi][ni], aHi[mi], bLo[ni]);
                    MMA16816(c[mi][ni], aLo[mi], bHi[ni]);
                }
        }
        __syncthreads();
    }

    // epilogue: direct STG (float2 per row-half)
    float* outp = (bx < 2) ? g_k : g_v;
    int cb = (bx & 1) * 128 + wn * 32 + (lane & 3) * 2;
#pragma unroll
    for (int mi = 0; mi < 4; mi++) {
        size_t r0 = m0 + wm * 64 + mi * 16 + (lane >> 2);
#pragma unroll
        for (int ni = 0; ni < 4; ni++) {
            int col = cb + ni * 8;
            *(float2*)&outp[r0 * 256 + col]       = make_float2(c[mi][ni][0], c[mi][ni][1]);
            *(float2*)&outp[(r0 + 8) * 256 + col] = make_float2(c[mi][ni][2], c[mi][ni][3]);
        }
    }
}

// ---------------- vsum ----------------
__global__ void zero_vsum_kernel() {
    int i = blockIdx.x * 1024 + threadIdx.x;
    if (i < B_ * DIM_) g_vsum[i] = 0.f;
}
__global__ __launch_bounds__(256) void vsum_kernel() {
    int b = blockIdx.x, ch = blockIdx.y, t = threadIdx.x;
    const float* vp = g_v + ((size_t)b * N_ + ch * 256) * DIM_ + t;
    float s = 0.f;
#pragma unroll 4
    for (int j = 0; j < 256; j++) s += vp[(size_t)j * DIM_];
    atomicAdd(&g_vsum[b * DIM_ + t], s);
}

// ---------------- zero per-iteration accumulators ----------------
__global__ void zero_kernel() {
    int idx = blockIdx.x * blockDim.x + threadIdx.x;  // 520*256
    if (idx < B_ * IH_) g_S[idx] = 0.f;
    else g_upd[idx - B_ * IH_] = 0.f;
}

// ---------------- slots LN + q projection ----------------
__global__ __launch_bounds__(256) void slot_q_kernel(const float* __restrict__ g,
                                                     const float* __restrict__ bb,
                                                     const float* __restrict__ Wq) {
    __shared__ float sn[256];
    int row = blockIdx.x, t = threadIdx.x;
    float sv = g_slots[row * 256 + t];
    float2 r = blockReduceSum2(sv, sv * sv);
    float mean = r.x * (1.f / 256.f);
    float var  = r.y * (1.f / 256.f) - mean * mean;
    float inv  = rsqrtf(var + 1e-5f);
    sn[t] = (sv - mean) * inv * g[t] + bb[t];
    __syncthreads();
    const float4* w4 = (const float4*)(Wq + (size_t)t * 256);
    float acc = 0.f;
#pragma unroll 8
    for (int c = 0; c < 64; c++) {
        float4 w = w4[c];
        acc += w.x * sn[4 * c] + w.y * sn[4 * c + 1] + w.z * sn[4 * c + 2] + w.w * sn[4 * c + 3];
    }
    g_q[row * 256 + t] = acc * SCALE_;
}

// ---------------- dots + joint softmax ----------------
#define DOTS_SMEM ((64 * 65 + 64 * 256 + 64 * 65) * 4)
__global__ __launch_bounds__(256) void dots_kernel(float* __restrict__ attn_out) {
    float* qs = dynsm;
    float* kt = dynsm + 64 * 65;
    float* ds = kt + 64 * 256;
    int b = blockIdx.y, jt = blockIdx.x, t = threadIdx.x;

    for (int idx = t; idx < 4096; idx += 256) {
        int i = idx >> 8, c = idx & 255;
        qs[(i * 4 + (c >> 6)) * 65 + (c & 63)] = g_q[(b * KSLOT_ + i) * 256 + c];
    }
    const float4* kb = (const float4*)(g_k + ((size_t)b * N_ + jt * 64) * DIM_);
    for (int idx = t; idx < 4096; idx += 256) ((float4*)kt)[idx] = kb[idx];
    __syncthreads();

    int i = t & 15, j0 = t >> 4;
    const float* q0 = qs + (i * 4 + 0) * 65;
    const float* q1 = qs + (i * 4 + 1) * 65;
    const float* q2 = qs + (i * 4 + 2) * 65;
    const float* q3 = qs + (i * 4 + 3) * 65;
#pragma unroll
    for (int jm = 0; jm < 4; jm++) {
        int j = j0 + jm * 16;
        const float* kr = kt + j * 256;
        float a0 = 0.f, a1 = 0.f, a2 = 0.f, a3 = 0.f;
#pragma unroll 16
        for (int d = 0; d < 64; d++) {
            a0 += q0[d] * kr[d];
            a1 += q1[d] * kr[64 + d];
            a2 += q2[d] * kr[128 + d];
            a3 += q3[d] * kr[192 + d];
        }
        ds[(i * 4 + 0) * 65 + j] = a0;
        ds[(i * 4 + 1) * 65 + j] = a1;
        ds[(i * 4 + 2) * 65 + j] = a2;
        ds[(i * 4 + 3) * 65 + j] = a3;
    }
    __syncthreads();

    if (t < 64) {
        float mx = -1e30f;
        for (int ih = 0; ih < 64; ih++) mx = fmaxf(mx, ds[ih * 65 + t]);
        float sum = 0.f;
        for (int ih = 0; ih < 64; ih++) {
            float e = expf(ds[ih * 65 + t] - mx);
            ds[ih * 65 + t] = e;
            sum += e;
        }
        float inv = 1.f / sum;
        for (int ih = 0; ih < 64; ih++) ds[ih * 65 + t] *= inv;
    }
    __syncthreads();

    for (int idx = t; idx < 4096; idx += 256) {
        int ih = idx >> 6, jl = idx & 63;
        g_attn[((size_t)b * IH_ + ih) * N_ + jt * 64 + jl] = ds[ih * 65 + jl];
    }
    if (t < 64) {
        float s = 0.f;
        for (int jl = 0; jl < 64; jl++) s += ds[t * 65 + jl];
        atomicAdd(&g_S[b * IH_ + t], s);
    }
    if (attn_out) {
        for (int idx = t; idx < 1024; idx += 256) {
            int i2 = idx >> 6, jl = idx & 63;
            float m = 0.25f * (ds[(i2 * 4 + 0) * 65 + jl] + ds[(i2 * 4 + 1) * 65 + jl] +
                               ds[(i2 * 4 + 2) * 65 + jl] + ds[(i2 * 4 + 3) * 65 + jl]);
            attn_out[((size_t)b * KSLOT_ + i2) * N_ + jt * 64 + jl] = m;
        }
    }
}

// ---------------- updates accumulation ----------------
#define UPD_SMEM ((64 * 65 + 64 * 256) * 4)
__global__ __launch_bounds__(256) void upd_kernel() {
    float* a_s = dynsm;
    float* v_s = dynsm + 64 * 65;
    int b = blockIdx.y, jc = blockIdx.x, t = threadIdx.x;
    int d = t & 63, ihg = t >> 6;
    float acc[16];
#pragma unroll
    for (int m = 0; m < 16; m++) acc[m] = 0.f;

    for (int sub = 0; sub < 8; sub++) {
        int j0 = jc * 512 + sub * 64;
        __syncthreads();
        for (int idx = t; idx < 4096; idx += 256) {
            int ih = idx >> 6, jl = idx & 63;
            a_s[ih * 65 + jl] = g_attn[((size_t)b * IH_ + ih) * N_ + j0 + jl];
        }
        const float4* vb = (const float4*)(g_v + ((size_t)b * N_ + j0) * DIM_);
        for (int idx = t; idx < 4096; idx += 256) ((float4*)v_s)[idx] = vb[idx];
        __syncthreads();
#pragma unroll 4
        for (int jl = 0; jl < 64; jl++) {
            float vh[4] = {v_s[jl * 256 + d], v_s[jl * 256 + 64 + d],
                           v_s[jl * 256 + 128 + d], v_s[jl * 256 + 192 + d]};
#pragma unroll
            for (int m = 0; m < 16; m++)
                acc[m] += a_s[(ihg * 16 + m) * 65 + jl] * vh[m & 3];
        }
    }
#pragma unroll
    for (int m = 0; m < 16; m++)
        atomicAdd(&g_upd[(b * IH_ + ihg * 16 + m) * DH_ + d], acc[m]);
}

// ---------------- GRU (8 rows per block) ----------------
__global__ __launch_bounds__(256) void gru_kernel(const float* __restrict__ w_ih,
                                                  const float* __restrict__ w_hh,
                                                  const float* __restrict__ b_ih,
                                                  const float* __restrict__ b_hh) {
    __shared__ float u[8][256];
    __shared__ float hp[8][256];
    int row0 = blockIdx.x * 8, t = threadIdx.x;
    int b = row0 >> 4;
#pragma unroll
    for (int r = 0; r < 8; r++) {
        int row = row0 + r;
        int ih = (row & 15) * 4 + (t >> 6);
        float upd = g_upd[(b * IH_ + ih) * DH_ + (t & 63)];
        float Sv  = g_S[b * IH_ + ih];
        u[r][t]  = (upd + EPSW_ * g_vsum[b * 256 + t]) / (Sv + (float)N_ * EPSW_);
        hp[r][t] = g_slots[(size_t)row * 256 + t];
    }
    __syncthreads();

    float s0a[8], s1a[8], gi2[8], gh2[8];
#pragma unroll
    for (int r = 0; r < 8; r++) { s0a[r] = 0.f; s1a[r] = 0.f; gi2[r] = 0.f; gh2[r] = 0.f; }

    const float4* wi0 = (const float4*)(w_ih + (size_t)t * 256);
    const float4* wi1 = (const float4*)(w_ih + (size_t)(256 + t) * 256);
    const float4* wi2 = (const float4*)(w_ih + (size_t)(512 + t) * 256);
    const float4* wh0 = (const float4*)(w_hh + (size_t)t * 256);
    const float4* wh1 = (const float4*)(w_hh + (size_t)(256 + t) * 256);
    const float4* wh2 = (const float4*)(w_hh + (size_t)(512 + t) * 256);

    for (int c = 0; c < 64; c++) {
        float4 a0 = wi0[c], a1 = wi1[c], a2 = wi2[c];
        float4 h0 = wh0[c], h1v = wh1[c], h2 = wh2[c];
#pragma unroll
        for (int r = 0; r < 8; r++) {
            float4 uu = *(const float4*)&u[r][4 * c];
            float4 hh = *(const float4*)&hp[r][4 * c];
            s0a[r] += a0.x * uu.x + a0.y * uu.y + a0.z * uu.z + a0.w * uu.w
                    + h0.x * hh.x + h0.y * hh.y + h0.z * hh.z + h0.w * hh.w;
            s1a[r] += a1.x * uu.x + a1.y * uu.y + a1.z * uu.z + a1.w * uu.w
                    + h1v.x * hh.x + h1v.y * hh.y + h1v.z * hh.z + h1v.w * hh.w;
            gi2[r] += a2.x * uu.x + a2.y * uu.y + a2.z * uu.z + a2.w * uu.w;
            gh2[r] += h2.x * hh.x + h2.y * hh.y + h2.z * hh.z + h2.w * hh.w;
        }
    }
    float bi0 = b_ih[t] + b_hh[t];
    float bi1 = b_ih[256 + t] + b_hh[256 + t];
    float bi2 = b_ih[512 + t], bh2 = b_hh[512 + t];
#pragma unroll
    for (int r = 0; r < 8; r++) {
        float rg = 1.f / (1.f + expf(-(s0a[r] + bi0)));
        float z  = 1.f / (1.f + expf(-(s1a[r] + bi1)));
        float n  = tanhf(gi2[r] + bi2 + rg * (gh2[r] + bh2));
        g_slots[(size_t)(row0 + r) * 256 + t] = (1.f - z) * n + z * hp[r][t];
    }
}

// ---------------- FF (8 rows per block) ----------------
__global__ __launch_bounds__(256) void ff_kernel(const float* __restrict__ g,
                                                 const float* __restrict__ bb,
                                                 const float* __restrict__ W1,
                                                 const float* __restrict__ b1,
                                                 const float* __restrict__ W2,
                                                 const float* __restrict__ b2) {
    __shared__ float h1[8][256];
    __shared__ float a_s[8][1024];
    int row0 = blockIdx.x * 8, t = threadIdx.x;
    int w = t >> 5, l = t & 31;

    {   // LN: warp w -> row w
        int row = row0 + w;
        const float* sp = g_slots + (size_t)row * 256;
        float4 x0 = *(const float4*)(sp + l * 8);
        float4 x1 = *(const float4*)(sp + l * 8 + 4);
        float s = x0.x + x0.y + x0.z + x0.w + x1.x + x1.y + x1.z + x1.w;
        float q = x0.x * x0.x + x0.y * x0.y + x0.z * x0.z + x0.w * x0.w
                + x1.x * x1.x + x1.y * x1.y + x1.z * x1.z + x1.w * x1.w;
#pragma unroll
        for (int o = 16; o; o >>= 1) {
            s += __shfl_xor_sync(0xffffffffu, s, o);
            q += __shfl_xor_sync(0xffffffffu, q, o);
        }
        float mean = s * (1.f / 256.f);
        float var  = q * (1.f / 256.f) - mean * mean;
        float inv  = rsqrtf(var + 1e-5f);
        int c0 = l * 8;
        float xv[8] = {x0.x, x0.y, x0.z, x0.w, x1.x, x1.y, x1.z, x1.w};
#pragma unroll
        for (int e = 0; e < 8; e++)
            h1[w][c0 + e] = (xv[e] - mean) * inv * g[c0 + e] + bb[c0 + e];
    }
    __syncthreads();

    float acc[4][8];
#pragma unroll
    for (int m = 0; m < 4; m++)
#pragma unroll
        for (int r = 0; r < 8; r++) acc[m][r] = 0.f;

    const float4* w1p0 = (const float4*)(W1 + (size_t)t * 256);
    const float4* w1p1 = (const float4*)(W1 + (size_t)(t + 256) * 256);
    const float4* w1p2 = (const float4*)(W1 + (size_t)(t + 512) * 256);
    const float4* w1p3 = (const float4*)(W1 + (size_t)(t + 768) * 256);
    for (int c = 0; c < 64; c++) {
        float4 wv0 = w1p0[c], wv1 = w1p1[c], wv2 = w1p2[c], wv3 = w1p3[c];
#pragma unroll
        for (int r = 0; r < 8; r++) {
            float4 hh = *(const float4*)&h1[r][4 * c];
            acc[0][r] += wv0.x * hh.x + wv0.y * hh.y + wv0.z * hh.z + wv0.w * hh.w;
            acc[1][r] += wv1.x * hh.x + wv1.y * hh.y + wv1.z * hh.z + wv1.w * hh.w;
            acc[2][r] += wv2.x * hh.x + wv2.y * hh.y + wv2.z * hh.z + wv2.w * hh.w;
            acc[3][r] += wv3.x * hh.x + wv3.y * hh.y + wv3.z * hh.z + wv3.w * hh.w;
        }
    }
#pragma unroll
    for (int m = 0; m < 4; m++) {
        float bv = b1[m * 256 + t];
#pragma unroll
        for (int r = 0; r < 8; r++) {
            float v = acc[m][r] + bv;
            a_s[r][m * 256 + t] = 0.5f * v * (1.f + erff(v * 0.70710678118654752f));
        }
    }
    __syncthreads();

    float o[8];
#pragma unroll
    for (int r = 0; r < 8; r++) o[r] = 0.f;
    const float4* w2p = (const float4*)(W2 + (size_t)t * 1024);
    for (int c = 0; c < 256; c++) {
        float4 wv = w2p[c];
#pragma unroll
        for (int r = 0; r < 8; r++) {
            float4 aa = *(const float4*)&a_s[r][4 * c];
            o[r] += wv.x * aa.x + wv.y * aa.y + wv.z * aa.z + wv.w * aa.w;
        }
    }
    float bt = b2[t];
#pragma unroll
    for (int r = 0; r < 8; r++)
        g_slots[(size_t)(row0 + r) * 256 + t] += o[r] + bt;
}

// ---------------- launch ----------------
extern "C" void kernel_launch(void* const* d_in, const int* in_sizes, int n_in,
                              void* d_out, int out_size) {
    const float* inputs  = (const float*)d_in[0];
    const float* cond    = (const float*)d_in[1];
    const float* to_q_w  = (const float*)d_in[2];
    const float* to_k_w  = (const float*)d_in[3];
    const float* to_v_w  = (const float*)d_in[4];
    const float* w_ih    = (const float*)d_in[5];
    const float* w_hh    = (const float*)d_in[6];
    const float* b_ih    = (const float*)d_in[7];
    const float* b_hh    = (const float*)d_in[8];
    const float* ln_in_g = (const float*)d_in[9];
    const float* ln_in_b = (const float*)d_in[10];
    const float* ln_s_g  = (const float*)d_in[11];
    const float* ln_s_b  = (const float*)d_in[12];
    const float* ff_g    = (const float*)d_in[13];
    const float* ff_b    = (const float*)d_in[14];
    const float* ff_w1   = (const float*)d_in[15];
    const float* ff_b1   = (const float*)d_in[16];
    const float* ff_w2   = (const float*)d_in[17];
    const float* ff_b2   = (const float*)d_in[18];

    float* out_slots = (float*)d_out;
    float* out_attn  = out_slots + (size_t)B_ * KSLOT_ * DIM_;

    void* pSlots = nullptr;
    cudaGetSymbolAddress(&pSlots, g_slots);

    cudaFuncSetAttribute(dots_kernel, cudaFuncAttributeMaxDynamicSharedMemorySize, DOTS_SMEM);
    cudaFuncSetAttribute(upd_kernel,  cudaFuncAttributeMaxDynamicSharedMemorySize, UPD_SMEM);
    cudaFuncSetAttribute(proj_mma_kernel, cudaFuncAttributeMaxDynamicSharedMemorySize, PROJ_SMEM);

    ln_in_kernel<<<B_ * N_, 256>>>(inputs, ln_in_g, ln_in_b);
    wconv_kernel<<<384, 1024>>>(to_k_w, to_v_w);
    proj_mma_kernel<<<dim3(4, 1024), 256, PROJ_SMEM>>>();
    zero_vsum_kernel<<<8, 1024>>>();
    vsum_kernel<<<dim3(B_, 16), 256>>>();
    cudaMemcpyAsync(pSlots, cond, (size_t)B_ * KSLOT_ * DIM_ * sizeof(float),
                    cudaMemcpyDeviceToDevice, 0);

    for (int it = 0; it < ITERS_; it++) {
        zero_kernel<<<520, 256>>>();
        slot_q_kernel<<<B_ * KSLOT_, 256>>>(ln_s_g, ln_s_b, to_q_w);
        dots_kernel<<<dim3(64, B_), 256, DOTS_SMEM>>>(it == ITERS_ - 1 ? out_attn : (float*)nullptr);
        upd_kernel<<<dim3(8, B_), 256, UPD_SMEM>>>();
        gru_kernel<<<64, 256>>>(w_ih, w_hh, b_ih, b_hh);
        ff_kernel<<<64, 256>>>(ff_g, ff_b, ff_w1, ff_b1, ff_w2, ff_b2);
    }
    cudaMemcpyAsync(d_out, pSlots, (size_t)B_ * KSLOT_ * DIM_ * sizeof(float),
                    cudaMemcpyDeviceToDevice, 0);
}